// round 7
// baseline (speedup 1.0000x reference)
#include <cuda_runtime.h>
#include <cuda_bf16.h>

// WTA2D: per (B,C) row of H*W=3136 fp32, t = 313th-largest, out = (t > x) ? x : 0.
//
// One CTA (256 thr) per row, row in registers (16 keys/thread).
// ONE 2048-bucket shared ATOMIC histogram of the top 11 key bits resolves the
// prefix; the crossing bucket is typically ~30-40 elems. Fast tail: gather <=64
// candidates from registers, warp-0 ballot bisection over the remaining 21 bits
// (2 candidates/lane). Generic fallback (compact + 4-bit rounds) if the bucket
// exceeds 64 elements.

#define NROW 3136
#define KSEL 313u
#define HBITS 11
#define HSIZE (1 << HBITS)          // 2048
#define HSHIFT (32 - HBITS)         // 21

__device__ __forceinline__ unsigned f2k(float f) {
    unsigned u = __float_as_uint(f);
    return (u & 0x80000000u) ? ~u : (u | 0x80000000u);
}
__device__ __forceinline__ float k2f(unsigned k) {
    unsigned u = (k & 0x80000000u) ? (k ^ 0x80000000u) : ~k;
    return __uint_as_float(u);
}

__global__ void __launch_bounds__(256, 6)
wta2d_kernel(const float* __restrict__ x, float* __restrict__ out) {
    const int tid  = threadIdx.x;
    const int lane = tid & 31;
    const int warp = tid >> 5;
    const size_t base = (size_t)blockIdx.x * NROW;

    __shared__ unsigned hist[HSIZE];        // 8KB
    __shared__ unsigned buf[NROW];          // fallback only
    __shared__ uint4 wsum[8][4];            // fallback only
    __shared__ unsigned warpcnt[8];
    __shared__ unsigned sb_d, sb_rank, sb_m, sb_tkey;
    __shared__ unsigned gbuf[64];
    __shared__ int gcount;

    // ---- zero histogram (2 x STS.128 per thread) ----
    {
        uint4 z = make_uint4(0u, 0u, 0u, 0u);
        uint4* h4 = reinterpret_cast<uint4*>(hist);
        h4[tid] = z;
        h4[tid + 256] = z;
    }
    if (tid == 0) gcount = 0;

    // ---- load row -> keys in registers ----
    unsigned key[16];
    const bool has4 = (tid < 16);
    const float4* xin = reinterpret_cast<const float4*>(x + base);
#pragma unroll
    for (int s = 0; s < 4; ++s) {
        int p = tid + s * 256;
        if (s < 3 || has4) {
            float4 f = xin[p];
            key[4*s+0] = f2k(f.x); key[4*s+1] = f2k(f.y);
            key[4*s+2] = f2k(f.z); key[4*s+3] = f2k(f.w);
        } else {
            key[4*s+0] = key[4*s+1] = key[4*s+2] = key[4*s+3] = 0u;
        }
    }
    __syncthreads();                        // zeros visible

    // ---- 11-bit digit histogram (shared atomics) ----
#pragma unroll
    for (int j = 0; j < 16; ++j) {
        bool valid = (j < 12) || has4;
        if (valid) atomicAdd(&hist[key[j] >> HSHIFT], 1u);
    }
    __syncthreads();

    // ---- pick crossing bucket among 2048 (thread owns 8: hist[tid*8..]) ----
    {
        const uint4* h4 = reinterpret_cast<const uint4*>(hist) + tid * 2;
        uint4 v0 = h4[0], v1 = h4[1];
        unsigned cc[8] = { v0.x, v0.y, v0.z, v0.w, v1.x, v1.y, v1.z, v1.w };
        unsigned tot = cc[0]+cc[1]+cc[2]+cc[3]+cc[4]+cc[5]+cc[6]+cc[7];
        unsigned s = tot;                   // warp suffix-inclusive sum
#pragma unroll
        for (int off = 1; off <= 16; off <<= 1) {
            unsigned v = __shfl_down_sync(0xFFFFFFFFu, s, off);
            if (lane + off < 32) s += v;
        }
        if (lane == 0) warpcnt[warp] = s;
        __syncthreads();
        unsigned above = s - tot;           // higher lanes in my warp
#pragma unroll
        for (int w = 0; w < 8; ++w) if (w > warp) above += warpcnt[w];
        unsigned run = above;               // walk my 8 buckets high -> low
#pragma unroll
        for (int j = 7; j >= 0; --j) {
            unsigned nr = run + cc[j];
            if (nr >= KSEL && run < KSEL) {
                sb_d    = (unsigned)(tid * 8 + j);
                sb_rank = KSEL - run;
                sb_m    = cc[j];
            }
            run = nr;
        }
    }
    __syncthreads();
    const unsigned d11 = sb_d;              // key >> 21 == d11
    const unsigned rk2 = sb_rank;
    const unsigned m2  = sb_m;

    if (m2 <= 64u) {
        // ---- fast tail: gather from registers, bisect low 21 bits ----
#pragma unroll
        for (int j = 0; j < 16; ++j) {
            bool valid = (j < 12) || has4;
            if (valid && (key[j] >> HSHIFT) == d11)
                gbuf[atomicAdd(&gcount, 1)] = key[j];
        }
        __syncthreads();
        if (warp == 0) {
            int n = gcount;
            unsigned ck0 = (lane      < n) ? gbuf[lane]      : 0u;
            unsigned ck1 = (lane + 32 < n) ? gbuf[lane + 32] : 0u;
            bool a0 = (lane < n), a1 = (lane + 32 < n);
            unsigned r = rk2;
            unsigned tk = d11 << HSHIFT;
#pragma unroll
            for (int b = HSHIFT - 1; b >= 0; --b) {
                bool bit0 = ((ck0 >> b) & 1u) != 0u;
                bool bit1 = ((ck1 >> b) & 1u) != 0u;
                unsigned c = __popc(__ballot_sync(0xFFFFFFFFu, a0 && bit0))
                           + __popc(__ballot_sync(0xFFFFFFFFu, a1 && bit1));
                if (c >= r) { a0 = a0 && bit0; a1 = a1 && bit1; tk |= (1u << b); }
                else        { r -= c; a0 = a0 && !bit0; a1 = a1 && !bit1; }
            }
            if (lane == 0) sb_tkey = tk;
        }
        __syncthreads();
    } else {
        // ---- generic fallback: compact bucket, 4-bit rounds ----
        unsigned mycnt = 0;
#pragma unroll
        for (int j = 0; j < 16; ++j) {
            bool valid = (j < 12) || has4;
            mycnt += (valid && (key[j] >> HSHIFT) == d11) ? 1u : 0u;
        }
        unsigned isum = mycnt;
#pragma unroll
        for (int off = 1; off <= 16; off <<= 1) {
            unsigned v = __shfl_up_sync(0xFFFFFFFFu, isum, off);
            if (lane >= off) isum += v;
        }
        if (lane == 31) warpcnt[warp] = isum;
        __syncthreads();
        unsigned pos = isum - mycnt;
#pragma unroll
        for (int w = 0; w < 8; ++w) pos += (w < warp) ? warpcnt[w] : 0u;
#pragma unroll
        for (int j = 0; j < 16; ++j) {
            bool valid = (j < 12) || has4;
            if (valid && (key[j] >> HSHIFT) == d11) buf[pos++] = key[j];
        }
        __syncthreads();

        unsigned prefix = d11, rk = rk2, mcur = m2;
        int shift = HSHIFT - 4;             // 17, 13, 9, 5, 1, ...
        while (mcur > 32 && shift >= 0) {
            unsigned long long acc = 0ull;
            int top = shift + 4;
            for (unsigned i = tid; i < m2; i += 256) {
                unsigned k = buf[i];
                if ((k >> top) == prefix) acc += 1ull << (((k >> shift) & 15u) * 4u);
            }
            {
                unsigned lo = (unsigned)acc, hi = (unsigned)(acc >> 32);
                unsigned r0 = (lo & 0x0F0F0F0Fu);
                unsigned r1 = ((lo >> 4) & 0x0F0F0F0Fu);
                unsigned r2 = (hi & 0x0F0F0F0Fu);
                unsigned r3 = ((hi >> 4) & 0x0F0F0F0Fu);
#pragma unroll
                for (int off = 1; off <= 4; off <<= 1) {
                    r0 += __shfl_xor_sync(0xFFFFFFFFu, r0, off);
                    r1 += __shfl_xor_sync(0xFFFFFFFFu, r1, off);
                    r2 += __shfl_xor_sync(0xFFFFFFFFu, r2, off);
                    r3 += __shfl_xor_sync(0xFFFFFFFFu, r3, off);
                }
                if ((lane & 7) == 0) wsum[warp][lane >> 3] = make_uint4(r0, r1, r2, r3);
            }
            __syncthreads();
            if (warp == 0) {
                unsigned cnt = 0;
                if (lane < 16) {
                    int word = (lane & 1) | ((lane >> 3) << 1);
                    int sh   = ((lane & 7) >> 1) * 8;
#pragma unroll
                    for (int w = 0; w < 8; ++w)
#pragma unroll
                        for (int g = 0; g < 4; ++g) {
                            const unsigned* ws = reinterpret_cast<const unsigned*>(&wsum[w][g]);
                            cnt += (ws[word] >> sh) & 0xFFu;
                        }
                }
                unsigned ssum = cnt;
#pragma unroll
                for (int off = 1; off <= 8; off <<= 1) {
                    unsigned v = __shfl_down_sync(0xFFFFFFFFu, ssum, off);
                    if (lane + off < 16) ssum += v;
                }
                if (lane < 16 && ssum >= rk && (ssum - cnt) < rk) {
                    sb_d    = (prefix << 4) | (unsigned)lane;
                    sb_rank = rk - (ssum - cnt);
                    sb_m    = cnt;
                }
            }
            __syncthreads();
            prefix = sb_d; rk = sb_rank; mcur = sb_m;
            shift -= 4;
        }

        int rem = shift + 4;
        if (rem > 0) {
            if (tid == 0) gcount = 0;
            __syncthreads();
            for (unsigned i = tid; i < m2; i += 256) {
                unsigned k = buf[i];
                if ((k >> rem) == prefix) {
                    int p = atomicAdd(&gcount, 1);
                    if (p < 32) gbuf[p] = k;
                }
            }
            __syncthreads();
            if (warp == 0) {
                int n = gcount; if (n > 32) n = 32;
                unsigned ck = (lane < n) ? gbuf[lane] : 0u;
                bool alive = (lane < n);
                unsigned r = rk;
                unsigned tk = prefix << rem;
                for (int b = rem - 1; b >= 0; --b) {
                    bool bit = ((ck >> b) & 1u) != 0u;
                    unsigned bal = __ballot_sync(0xFFFFFFFFu, alive && bit);
                    unsigned c = __popc(bal);
                    if (c >= r) { alive = alive && bit; tk |= (1u << b); }
                    else        { r -= c; alive = alive && !bit; }
                }
                if (lane == 0) sb_tkey = tk;
            }
        } else {
            if (tid == 0) sb_tkey = prefix;
        }
        __syncthreads();
    }
    const unsigned tkey = sb_tkey;

    // ---- mask + store (key < tkey  <=>  x < t) ----
    float4* po = reinterpret_cast<float4*>(out + base);
#pragma unroll
    for (int s2 = 0; s2 < 4; ++s2) {
        int p = tid + s2 * 256;
        if (s2 < 3 || has4) {
            float4 o;
            o.x = (key[4*s2+0] < tkey) ? k2f(key[4*s2+0]) : 0.0f;
            o.y = (key[4*s2+1] < tkey) ? k2f(key[4*s2+1]) : 0.0f;
            o.z = (key[4*s2+2] < tkey) ? k2f(key[4*s2+2]) : 0.0f;
            o.w = (key[4*s2+3] < tkey) ? k2f(key[4*s2+3]) : 0.0f;
            po[p] = o;
        }
    }
}

extern "C" void kernel_launch(void* const* d_in, const int* in_sizes, int n_in,
                              void* d_out, int out_size) {
    const float* x = (const float*)d_in[0];
    float* out = (float*)d_out;
    int rows = in_sizes[0] / NROW;   // 16384
    wta2d_kernel<<<rows, 256>>>(x, out);
}

// round 8
// speedup vs baseline: 1.2883x; 1.2883x over previous
#include <cuda_runtime.h>
#include <cuda_bf16.h>

// WTA2D: per (B,C) row of H*W=3136 fp32, t = 313th-largest, out = (t > x) ? x : 0.
//
// One CTA (256 thr) per row, row in registers as raw uint bits (16/thread).
// Round 1: 256-bucket shared atomic histogram of RAW top byte (u>>24); the
//          key-order permutation is folded into the warp-0 pick walk.
// Round 2: 256-bucket histogram of 2nd byte XOR sign-mask (== true key byte)
//          over the winning bucket -> 16-bit key prefix, ~10-40 elems.
// Tail: gather <=64 candidates (computing full keys only for those), warp-0
//       ballot bisection over low 16 bits. Output via float compare vs k2f(t).
// Generic fallback (compact + 4-bit rounds) if the bucket exceeds 64 elems.

#define NROW 3136
#define KSEL 313u

__device__ __forceinline__ unsigned f2k(float f) {
    unsigned u = __float_as_uint(f);
    return (u & 0x80000000u) ? ~u : (u | 0x80000000u);
}
__device__ __forceinline__ unsigned u2k(unsigned u) {
    return (u & 0x80000000u) ? ~u : (u | 0x80000000u);
}
__device__ __forceinline__ float k2f(unsigned k) {
    unsigned u = (k & 0x80000000u) ? (k ^ 0x80000000u) : ~k;
    return __uint_as_float(u);
}

__global__ void __launch_bounds__(256, 6)
wta2d_kernel(const float* __restrict__ x, float* __restrict__ out) {
    const int tid  = threadIdx.x;
    const int lane = tid & 31;
    const int warp = tid >> 5;
    const size_t base = (size_t)blockIdx.x * NROW;

    __shared__ unsigned histA[256];
    __shared__ unsigned histB[256];
    __shared__ unsigned buf[NROW];          // fallback only
    __shared__ uint4 wsum[8][4];            // fallback only
    __shared__ unsigned warpcnt[8];         // fallback only
    __shared__ unsigned sb_d, sb_rank, sb_m, sb_tkey;
    __shared__ unsigned gbuf[64];
    __shared__ int gcount;

    histA[tid] = 0u;
    histB[tid] = 0u;
    if (tid == 0) gcount = 0;

    // ---- load row -> raw uint bits in registers ----
    unsigned u[16];
    const bool has4 = (tid < 16);
    const uint4* xin = reinterpret_cast<const uint4*>(x + base);
#pragma unroll
    for (int s = 0; s < 4; ++s) {
        int p = tid + s * 256;
        if (s < 3 || has4) {
            uint4 f = xin[p];
            u[4*s+0] = f.x; u[4*s+1] = f.y; u[4*s+2] = f.z; u[4*s+3] = f.w;
        } else {
            u[4*s+0] = u[4*s+1] = u[4*s+2] = u[4*s+3] = 0u;
        }
    }
    __syncthreads();                        // zeros visible

    // ---- round 1: raw top-byte histogram ----
#pragma unroll
    for (int j = 0; j < 16; ++j) {
        bool valid = (j < 12) || has4;
        if (valid) atomicAdd(&histA[u[j] >> 24], 1u);
    }
    __syncthreads();

    if (warp == 0) {
        // ordered slot o (0 = highest key): o<128 -> u8=127-o (positives
        // descending), o>=128 -> u8=o (negatives descending).
        int o0 = lane * 8;
        unsigned cc[8];
#pragma unroll
        for (int j = 0; j < 8; ++j) {
            int o = o0 + j;
            int u8 = (o < 128) ? (127 - o) : o;
            cc[j] = histA[u8];
        }
        unsigned tot = cc[0]+cc[1]+cc[2]+cc[3]+cc[4]+cc[5]+cc[6]+cc[7];
        unsigned p = tot;                   // inclusive prefix over lanes
#pragma unroll
        for (int off = 1; off <= 16; off <<= 1) {
            unsigned v = __shfl_up_sync(0xFFFFFFFFu, p, off);
            if (lane >= off) p += v;
        }
        unsigned run = p - tot;             // counts in lower-o slots
#pragma unroll
        for (int j = 0; j < 8; ++j) {
            unsigned nr = run + cc[j];
            if (nr >= KSEL && run < KSEL) {
                int o = o0 + j;
                unsigned u8 = (o < 128) ? (unsigned)(127 - o) : (unsigned)o;
                sb_d    = u8 | ((o >= 128) ? 256u : 0u);   // bit8 = negative region
                sb_rank = KSEL - run;
            }
            run = nr;
        }
    }
    __syncthreads();
    const unsigned du8 = sb_d & 0xFFu;
    const unsigned X   = (sb_d & 256u) ? 0xFFu : 0u;   // sign flip for 2nd byte

    // ---- round 2: key-2nd-byte histogram over bucket du8 ----
#pragma unroll
    for (int j = 0; j < 16; ++j) {
        bool valid = (j < 12) || has4;
        if (valid && (u[j] >> 24) == du8)
            atomicAdd(&histB[((u[j] >> 16) & 0xFFu) ^ X], 1u);
    }
    __syncthreads();

    if (warp == 0) {    // standard descending pick among 256 key-byte buckets
        unsigned rk1 = sb_rank;
        __syncwarp();
        const uint4* h4 = reinterpret_cast<const uint4*>(histB) + lane * 2;
        uint4 v0 = h4[0], v1 = h4[1];
        unsigned cc[8] = { v0.x, v0.y, v0.z, v0.w, v1.x, v1.y, v1.z, v1.w };
        unsigned tot = cc[0]+cc[1]+cc[2]+cc[3]+cc[4]+cc[5]+cc[6]+cc[7];
        unsigned s = tot;
#pragma unroll
        for (int off = 1; off <= 16; off <<= 1) {
            unsigned v = __shfl_down_sync(0xFFFFFFFFu, s, off);
            if (lane + off < 32) s += v;
        }
        unsigned run = s - tot;             // counts in higher buckets
#pragma unroll
        for (int j = 7; j >= 0; --j) {
            unsigned nr = run + cc[j];
            if (nr >= rk1 && run < rk1) {
                sb_d    = (unsigned)(lane * 8 + j);    // d2: key's 2nd byte
                sb_rank = rk1 - run;
                sb_m    = cc[j];
            }
            run = nr;
        }
    }
    __syncthreads();
    const unsigned d2  = sb_d;
    const unsigned rk2 = sb_rank;
    const unsigned m2  = sb_m;
    const unsigned K8  = X ? (255u - du8) : (du8 + 128u);  // key top byte
    const unsigned prefix16 = (K8 << 8) | d2;              // key >> 16
    const unsigned U16 = (du8 << 8) | (d2 ^ X);            // raw u >> 16

    if (m2 <= 64u) {
        // ---- fast tail: gather matching elems (keys computed only here) ----
#pragma unroll
        for (int j = 0; j < 16; ++j) {
            bool valid = (j < 12) || has4;
            if (valid && (u[j] >> 16) == U16)
                gbuf[atomicAdd(&gcount, 1)] = u2k(u[j]);
        }
        __syncthreads();
        if (warp == 0) {
            int n = gcount;
            unsigned ck0 = (lane      < n) ? gbuf[lane]      : 0u;
            unsigned ck1 = (lane + 32 < n) ? gbuf[lane + 32] : 0u;
            bool a0 = (lane < n), a1 = (lane + 32 < n);
            unsigned r = rk2;
            unsigned tk = prefix16 << 16;
#pragma unroll
            for (int b = 15; b >= 0; --b) {
                bool bit0 = ((ck0 >> b) & 1u) != 0u;
                bool bit1 = ((ck1 >> b) & 1u) != 0u;
                unsigned c = __popc(__ballot_sync(0xFFFFFFFFu, a0 && bit0))
                           + __popc(__ballot_sync(0xFFFFFFFFu, a1 && bit1));
                if (c >= r) { a0 = a0 && bit0; a1 = a1 && bit1; tk |= (1u << b); }
                else        { r -= c; a0 = a0 && !bit0; a1 = a1 && !bit1; }
            }
            if (lane == 0) sb_tkey = tk;
        }
        __syncthreads();
    } else {
        // ---- generic fallback: compact prefix16 bucket (key domain) ----
        unsigned mycnt = 0;
#pragma unroll
        for (int j = 0; j < 16; ++j) {
            bool valid = (j < 12) || has4;
            mycnt += (valid && (u[j] >> 16) == U16) ? 1u : 0u;
        }
        unsigned isum = mycnt;
#pragma unroll
        for (int off = 1; off <= 16; off <<= 1) {
            unsigned v = __shfl_up_sync(0xFFFFFFFFu, isum, off);
            if (lane >= off) isum += v;
        }
        if (lane == 31) warpcnt[warp] = isum;
        __syncthreads();
        unsigned pos = isum - mycnt;
#pragma unroll
        for (int w = 0; w < 8; ++w) pos += (w < warp) ? warpcnt[w] : 0u;
#pragma unroll
        for (int j = 0; j < 16; ++j) {
            bool valid = (j < 12) || has4;
            if (valid && (u[j] >> 16) == U16) buf[pos++] = u2k(u[j]);
        }
        __syncthreads();

        unsigned prefix = prefix16, rk = rk2, mcur = m2;
        int shift = 12;
        while (mcur > 32 && shift >= 0) {
            unsigned long long acc = 0ull;
            int top = shift + 4;
            for (unsigned i = tid; i < m2; i += 256) {
                unsigned k = buf[i];
                if ((k >> top) == prefix) acc += 1ull << (((k >> shift) & 15u) * 4u);
            }
            {
                unsigned lo = (unsigned)acc, hi = (unsigned)(acc >> 32);
                unsigned r0 = (lo & 0x0F0F0F0Fu);
                unsigned r1 = ((lo >> 4) & 0x0F0F0F0Fu);
                unsigned r2 = (hi & 0x0F0F0F0Fu);
                unsigned r3 = ((hi >> 4) & 0x0F0F0F0Fu);
#pragma unroll
                for (int off = 1; off <= 4; off <<= 1) {
                    r0 += __shfl_xor_sync(0xFFFFFFFFu, r0, off);
                    r1 += __shfl_xor_sync(0xFFFFFFFFu, r1, off);
                    r2 += __shfl_xor_sync(0xFFFFFFFFu, r2, off);
                    r3 += __shfl_xor_sync(0xFFFFFFFFu, r3, off);
                }
                if ((lane & 7) == 0) wsum[warp][lane >> 3] = make_uint4(r0, r1, r2, r3);
            }
            __syncthreads();
            if (warp == 0) {
                unsigned cnt = 0;
                if (lane < 16) {
                    int word = (lane & 1) | ((lane >> 3) << 1);
                    int sh   = ((lane & 7) >> 1) * 8;
#pragma unroll
                    for (int w = 0; w < 8; ++w)
#pragma unroll
                        for (int g = 0; g < 4; ++g) {
                            const unsigned* ws = reinterpret_cast<const unsigned*>(&wsum[w][g]);
                            cnt += (ws[word] >> sh) & 0xFFu;
                        }
                }
                unsigned ssum = cnt;
#pragma unroll
                for (int off = 1; off <= 8; off <<= 1) {
                    unsigned v = __shfl_down_sync(0xFFFFFFFFu, ssum, off);
                    if (lane + off < 16) ssum += v;
                }
                if (lane < 16 && ssum >= rk && (ssum - cnt) < rk) {
                    sb_d    = (prefix << 4) | (unsigned)lane;
                    sb_rank = rk - (ssum - cnt);
                    sb_m    = cnt;
                }
            }
            __syncthreads();
            prefix = sb_d; rk = sb_rank; mcur = sb_m;
            shift -= 4;
        }

        int rem = shift + 4;
        if (rem > 0) {
            if (tid == 0) gcount = 0;
            __syncthreads();
            for (unsigned i = tid; i < m2; i += 256) {
                unsigned k = buf[i];
                if ((k >> rem) == prefix) {
                    int p = atomicAdd(&gcount, 1);
                    if (p < 32) gbuf[p] = k;
                }
            }
            __syncthreads();
            if (warp == 0) {
                int n = gcount; if (n > 32) n = 32;
                unsigned ck = (lane < n) ? gbuf[lane] : 0u;
                bool alive = (lane < n);
                unsigned r = rk;
                unsigned tk = prefix << rem;
                for (int b = rem - 1; b >= 0; --b) {
                    bool bit = ((ck >> b) & 1u) != 0u;
                    unsigned bal = __ballot_sync(0xFFFFFFFFu, alive && bit);
                    unsigned c = __popc(bal);
                    if (c >= r) { alive = alive && bit; tk |= (1u << b); }
                    else        { r -= c; alive = alive && !bit; }
                }
                if (lane == 0) sb_tkey = tk;
            }
        } else {
            if (tid == 0) sb_tkey = prefix;
        }
        __syncthreads();
    }

    // ---- mask + store: float compare against threshold ----
    const float t = k2f(sb_tkey);
    float4* po = reinterpret_cast<float4*>(out + base);
#pragma unroll
    for (int s2 = 0; s2 < 4; ++s2) {
        int p = tid + s2 * 256;
        if (s2 < 3 || has4) {
            float4 o;
            float fx = __uint_as_float(u[4*s2+0]);
            float fy = __uint_as_float(u[4*s2+1]);
            float fz = __uint_as_float(u[4*s2+2]);
            float fw = __uint_as_float(u[4*s2+3]);
            o.x = (fx < t) ? fx : 0.0f;
            o.y = (fy < t) ? fy : 0.0f;
            o.z = (fz < t) ? fz : 0.0f;
            o.w = (fw < t) ? fw : 0.0f;
            po[p] = o;
        }
    }
}

extern "C" void kernel_launch(void* const* d_in, const int* in_sizes, int n_in,
                              void* d_out, int out_size) {
    const float* x = (const float*)d_in[0];
    float* out = (float*)d_out;
    int rows = in_sizes[0] / NROW;   // 16384
    wta2d_kernel<<<rows, 256>>>(x, out);
}